// round 9
// baseline (speedup 1.0000x reference)
#include <cuda_runtime.h>
#include <cuda_bf16.h>
#include <cstdint>

// BiLSTM-CRF forward, all fp32 (Viterbi argmax stability forbids low precision).
// Persistent recurrence: thread = 4 cells (2b x 2h) over full k; b-pair f32x2
// accumulators (h loads are natural b64, 1 wavefront/warp), duplicated-weight
// smem (no packs), zero intra-step synchronization.
//
// Shapes: V=50000 E=512 H=512 HD=1024 B=64 L=512 T=16, START=14 STOP=15

#define NEGV -10000.0f

typedef unsigned long long u64;

// ---------------- scratch (__device__ globals) ----------------------------
__device__ float g_G[(size_t)32768 * 4096];       // input-proj gates [l*64+b][dir*2048+g*512+h]
__device__ float g_Wt[(size_t)512 * 4096];        // Wih^T combined  [k][n]
__device__ float g_WhT[2][(size_t)512 * 2048];    // Whh^T per dir   [k][g*512+h]
__device__ float g_h[2][2][512][64];              // [parity][dir][k][b]  (b contiguous)
__device__ float g_hrow[(size_t)32768 * 1024];    // [l*64+b][dir*512+h]
__device__ float g_feats[(size_t)64 * 512 * 16];  // [b][l][t]
__device__ unsigned g_bar[2];                     // per-dir step barrier

// ---------------- helpers ---------------------------------------------------
__device__ __forceinline__ void ffma2(u64 &d, u64 a, u64 b) {
    asm("fma.rn.f32x2 %0, %1, %2, %0;" : "+l"(d) : "l"(a), "l"(b));
}
__device__ __forceinline__ u64 pack2(float x) {
    u64 r; asm("mov.b64 %0, {%1, %1};" : "=l"(r) : "f"(x)); return r;
}
__device__ __forceinline__ float2 unpack2(u64 v) {
    float2 f; asm("mov.b64 {%0, %1}, %2;" : "=f"(f.x), "=f"(f.y) : "l"(v)); return f;
}
__device__ __forceinline__ float sigf(float x) { return 1.0f / (1.0f + expf(-x)); }
__device__ __forceinline__ u64 ldcg64(const float* p) {
    u64 v; asm volatile("ld.global.cg.b64 %0, [%1];" : "=l"(v) : "l"(p)); return v;
}
__device__ __forceinline__ void cp16(unsigned dst_sm, const float* src) {
    asm volatile("cp.async.cg.shared.global [%0], [%1], 16;\n" :: "r"(dst_sm), "l"(src));
}
template <int N> __device__ __forceinline__ void cp_wait() {
    asm volatile("cp.async.wait_group %0;\n" :: "n"(N) : "memory");
}
__device__ __forceinline__ void cp_commit() {
    asm volatile("cp.async.commit_group;\n" ::: "memory");
}
__device__ __forceinline__ void bar_arrive(unsigned* p) {
    asm volatile("red.release.gpu.global.add.u32 [%0], %1;" :: "l"(p), "r"(1u) : "memory");
}
__device__ __forceinline__ unsigned ld_acq(const unsigned* p) {
    unsigned v; asm volatile("ld.acquire.gpu.global.u32 %0, [%1];" : "=r"(v) : "l"(p) : "memory");
    return v;
}

// ---------------- prep kernels ---------------------------------------------
__global__ void prepA(const float* __restrict__ wf, const float* __restrict__ wb,
                      const float* __restrict__ h0) {
    int idx = blockIdx.x * 256 + threadIdx.x;
    if (idx < 2) g_bar[idx] = 0;
    if (idx < 2097152) {                       // 512*4096
        int k = idx >> 12, n = idx & 4095;
        g_Wt[idx] = (n < 2048) ? wf[n * 512 + k] : wb[(n - 2048) * 512 + k];
    } else {
        int r2 = idx - 2097152;                // 2*512*64: transpose h0 -> [k][b]
        if (r2 < 65536) {
            int dir = r2 >> 15; int r = r2 & 32767;
            int k = r >> 6, b = r & 63;
            g_h[0][dir][k][b] = h0[((size_t)dir * 64 + b) * 512 + k];
        }
    }
}
__global__ void prepB(const float* __restrict__ whf, const float* __restrict__ whb) {
    int idx = blockIdx.x * 256 + threadIdx.x;  // 2*512*2048
    int dir = idx >> 20; int r = idx & ((1 << 20) - 1);
    int k = r >> 11, n = r & 2047;
    const float* w = dir ? whb : whf;
    g_WhT[dir][(size_t)k * 2048 + n] = w[n * 512 + k];
}

// ---------------- input projection GEMM (cp.async 2-stage) ------------------
__global__ void __launch_bounds__(256) gemm1(const int* __restrict__ sent,
                                             const float* __restrict__ embed,
                                             const float* __restrict__ bf,
                                             const float* __restrict__ bb) {
    __shared__ float As[2][128][16];
    __shared__ float Bs[2][16][128];
    __shared__ int toks[128];
    int tid = threadIdx.x;
    int n0 = blockIdx.x * 128;
    int m0 = blockIdx.y * 128;
    if (tid < 128) { int m = m0 + tid; toks[tid] = sent[(m & 63) * 512 + (m >> 6)]; }
    __syncthreads();
    int tx = tid & 15, ty = tid >> 4;
    unsigned smA = (unsigned)__cvta_generic_to_shared(&As[0][0][0]);
    unsigned smB = (unsigned)__cvta_generic_to_shared(&Bs[0][0][0]);

    u64 acc[8][4];
#pragma unroll
    for (int i = 0; i < 8; i++)
#pragma unroll
        for (int j = 0; j < 4; j++) acc[i][j] = 0ull;

    auto issue = [&](int k0, int buf) {
#pragma unroll
        for (int r = 0; r < 2; r++) {
            int idx = tid * 2 + r;
            int am = idx >> 2, aq = idx & 3;
            cp16(smA + (unsigned)(((buf * 128 + am) * 16 + aq * 4) * 4),
                 embed + (size_t)toks[am] * 512 + k0 + aq * 4);
            int bk = idx >> 5, bn = idx & 31;
            cp16(smB + (unsigned)(((buf * 16 + bk) * 128 + bn * 4) * 4),
                 g_Wt + (size_t)(k0 + bk) * 4096 + n0 + bn * 4);
        }
        cp_commit();
    };

    issue(0, 0);
    for (int c = 0; c < 32; c++) {
        cp_wait<0>();
        __syncthreads();
        if (c < 31) issue((c + 1) * 16, (c + 1) & 1);
        const int buf = c & 1;
#pragma unroll
        for (int k = 0; k < 16; k++) {
            u64 bv[4];
#pragma unroll
            for (int j = 0; j < 4; j++)
                bv[j] = *(const u64*)&Bs[buf][k][(j * 16 + tx) * 2];
#pragma unroll
            for (int i = 0; i < 8; i++) {
                u64 av = pack2(As[buf][ty * 8 + i][k]);
#pragma unroll
                for (int j = 0; j < 4; j++) ffma2(acc[i][j], av, bv[j]);
            }
        }
    }
#pragma unroll
    for (int j = 0; j < 4; j++) {
        int n = n0 + (j * 16 + tx) * 2;
        float2 bias;
        bias.x = (n < 2048) ? bf[n] : bb[n - 2048];
        bias.y = (n + 1 < 2048) ? bf[n + 1] : bb[n + 1 - 2048];
#pragma unroll
        for (int i = 0; i < 8; i++) {
            float2 v = unpack2(acc[i][j]);
            size_t row = (size_t)(m0 + ty * 8 + i);
            *(float2*)&g_G[row * 4096 + n] = make_float2(v.x + bias.x, v.y + bias.y);
        }
    }
}

// ---------------- persistent LSTM recurrence --------------------------------
// 128 blocks = 2 dirs x 64 h-tiles (8 h-cols). 128 threads: thread = (bp, hp)
// owns cells (2b x 2h) over full k=512. Weights duplicated (w,w) in smem;
// h streamed as b-pair b64 loads (1 wavefront/warp); c-state + G in registers.
__global__ void __launch_bounds__(128, 1) lstm_persist(const float* __restrict__ c0) {
    extern __shared__ float smf[];
    u64* Ws = (u64*)smf;             // [512][4 hp][8]: (g,ci) duplicated pairs
    const int tid = threadIdx.x;
    const int dir = blockIdx.x >> 6;
    const int h0  = (blockIdx.x & 63) * 8;
    const int bp  = tid >> 2;        // 0..31
    const int hp  = tid & 3;         // 0..3
    const int b0  = 2 * bp;

    const float* Wd = g_WhT[dir];
    for (int i = tid; i < 16384; i += 128) {
        int k = i >> 5, r = i & 31;
        int hh = r >> 3, g = (r >> 1) & 3, ci = r & 1;
        Ws[i] = pack2(Wd[(size_t)k * 2048 + g * 512 + h0 + 2 * hh + ci]);
    }
    float creg[2][2];
#pragma unroll
    for (int bi = 0; bi < 2; bi++)
#pragma unroll
        for (int ci = 0; ci < 2; ci++)
            creg[bi][ci] = c0[((size_t)dir * 64 + b0 + bi) * 512 + h0 + 2 * hp + ci];
    __syncthreads();

    const u64* wbase = Ws + hp * 8;

    for (int t = 0; t < 512; t++) {
        const int p = t & 1;
        const int l = dir ? (511 - t) : t;

        // G prefetch into registers (consumed ~8K cycles later)
        float2 gv[2][4];
#pragma unroll
        for (int bi = 0; bi < 2; bi++) {
            const float* Gp = g_G + ((size_t)l * 64 + b0 + bi) * 4096
                            + (size_t)dir * 2048 + h0 + 2 * hp;
#pragma unroll
            for (int g = 0; g < 4; g++) gv[bi][g] = *(const float2*)(Gp + g * 512);
        }

        const float* hb = &g_h[p][dir][0][b0];   // stride 64 floats per k
        u64 acc[4][2];
#pragma unroll
        for (int g = 0; g < 4; g++) { acc[g][0] = 0ull; acc[g][1] = 0ull; }

        u64 hv[2][16];
#pragma unroll
        for (int i = 0; i < 16; i++) hv[0][i] = ldcg64(hb + i * 64);

        for (int kb = 0; kb < 512; kb += 16) {
            const int cur = (kb >> 4) & 1;
            if (kb + 16 < 512) {
#pragma unroll
                for (int i = 0; i < 16; i++)
                    hv[cur ^ 1][i] = ldcg64(hb + (kb + 16 + i) * 64);
            }
#pragma unroll
            for (int i = 0; i < 16; i++) {
                const u64* wk = wbase + (kb + i) * 32;
                ulonglong2 w0 = *(const ulonglong2*)(wk);
                ulonglong2 w1 = *(const ulonglong2*)(wk + 2);
                ulonglong2 w2 = *(const ulonglong2*)(wk + 4);
                ulonglong2 w3 = *(const ulonglong2*)(wk + 6);
                u64 a = hv[cur][i];
                ffma2(acc[0][0], a, w0.x); ffma2(acc[0][1], a, w0.y);
                ffma2(acc[1][0], a, w1.x); ffma2(acc[1][1], a, w1.y);
                ffma2(acc[2][0], a, w2.x); ffma2(acc[2][1], a, w2.y);
                ffma2(acc[3][0], a, w3.x); ffma2(acc[3][1], a, w3.y);
            }
        }

        // fused LSTM pointwise: acc[g][ci] packs (b0, b1)
        float2 sg[4][2];
#pragma unroll
        for (int g = 0; g < 4; g++) {
            sg[g][0] = unpack2(acc[g][0]);
            sg[g][1] = unpack2(acc[g][1]);
        }
        float hcell[2][2];
#pragma unroll
        for (int bi = 0; bi < 2; bi++) {
#pragma unroll
            for (int ci = 0; ci < 2; ci++) {
                float iv = (bi ? sg[0][ci].y : sg[0][ci].x) + (ci ? gv[bi][0].y : gv[bi][0].x);
                float fv = (bi ? sg[1][ci].y : sg[1][ci].x) + (ci ? gv[bi][1].y : gv[bi][1].x);
                float gg = (bi ? sg[2][ci].y : sg[2][ci].x) + (ci ? gv[bi][2].y : gv[bi][2].x);
                float ov = (bi ? sg[3][ci].y : sg[3][ci].x) + (ci ? gv[bi][3].y : gv[bi][3].x);
                float cn = sigf(fv) * creg[bi][ci] + sigf(iv) * tanhf(gg);
                creg[bi][ci] = cn;
                hcell[bi][ci] = sigf(ov) * tanhf(cn);
            }
            *(float2*)&g_hrow[((size_t)l * 64 + b0 + bi) * 1024 + dir * 512 + h0 + 2 * hp] =
                make_float2(hcell[bi][0], hcell[bi][1]);
        }
        float* hn = &g_h[p ^ 1][dir][0][0];
#pragma unroll
        for (int ci = 0; ci < 2; ci++)
            *(float2*)&hn[(h0 + 2 * hp + ci) * 64 + b0] = make_float2(hcell[0][ci], hcell[1][ci]);

        // per-dir grid barrier
        if (t != 511) {
            __syncthreads();
            if (tid == 0) {
                bar_arrive(&g_bar[dir]);
                unsigned target = 64u * (unsigned)(t + 1);
                while (ld_acq(&g_bar[dir]) < target) { }
            }
            __syncthreads();
        }
    }
}

// ---------------- tag projection ---------------------------------------------
__global__ void __launch_bounds__(256) feats_kernel(const float* __restrict__ Wtag,
                                                    const float* __restrict__ btag) {
    int idx = blockIdx.x * 256 + threadIdx.x;   // 64*512*16
    int t = idx & 15;
    int l = (idx >> 4) & 511;
    int b = idx >> 13;
    const float4* hr = (const float4*)(g_hrow + (size_t)(l * 64 + b) * 1024);
    const float4* wr = (const float4*)(Wtag + (size_t)t * 1024);
    float a0 = 0.f, a1 = 0.f;
#pragma unroll 8
    for (int k = 0; k < 256; k += 2) {
        float4 x = hr[k],     w = wr[k];
        float4 y = hr[k + 1], v = wr[k + 1];
        a0 += x.x * w.x + x.y * w.y + x.z * w.z + x.w * w.w;
        a1 += y.x * v.x + y.y * v.y + y.z * v.z + y.w * v.w;
    }
    g_feats[((size_t)b * 512 + l) * 16 + t] = a0 + a1 + btag[t];
}

// ---------------- Viterbi -----------------------------------------------------
__global__ void __launch_bounds__(32) viterbi_kernel(const float* __restrict__ trans,
                                                     float* __restrict__ out) {
    int b = blockIdx.x;
    int lane = threadIdx.x;
    __shared__ unsigned char bp[512][16];
    __shared__ float smax[16];
    bool active = lane < 16;
    int row = active ? lane : 15;
    float tr[16];
#pragma unroll
    for (int j = 0; j < 16; j++) tr[j] = trans[row * 16 + j];
    float fv = (lane == 14) ? 0.0f : NEGV;   // START=14

    const float* fb = g_feats + (size_t)b * 512 * 16;
    for (int l = 0; l < 512; l++) {
        float best = -3.4e38f;
        int arg = 0;
#pragma unroll
        for (int j = 0; j < 16; j++) {
            float s = __shfl_sync(0xffffffffu, fv, j) + tr[j];
            if (s > best) { best = s; arg = j; }
        }
        float nf = best + fb[l * 16 + row];
        if (active) bp[l][lane] = (unsigned char)arg;
        fv = nf;
    }
    float term = fv + trans[15 * 16 + row];  // STOP=15
    if (active) smax[lane] = term;
    __syncwarp();
    if (lane == 0) {
        float best = smax[0]; int tag = 0;
        for (int j = 1; j < 16; j++) if (smax[j] > best) { best = smax[j]; tag = j; }
        out[b] = best;
        for (int l = 511; l >= 0; l--) {
            out[64 + b * 512 + l] = (float)tag;
            tag = bp[l][tag];
        }
    }
}

// ---------------- launch -------------------------------------------------------
extern "C" void kernel_launch(void* const* d_in, const int* in_sizes, int n_in,
                              void* d_out, int out_size) {
    const int*   sent  = (const int*)d_in[0];
    const float* embed = (const float*)d_in[1];
    const float* Wih_f = (const float*)d_in[2];
    const float* Whh_f = (const float*)d_in[3];
    const float* b_f   = (const float*)d_in[4];
    const float* Wih_b = (const float*)d_in[5];
    const float* Whh_b = (const float*)d_in[6];
    const float* b_b   = (const float*)d_in[7];
    const float* h0    = (const float*)d_in[8];
    const float* c0    = (const float*)d_in[9];
    const float* W_tag = (const float*)d_in[10];
    const float* b_tag = (const float*)d_in[11];
    const float* trans = (const float*)d_in[12];
    float* out = (float*)d_out;

    cudaFuncSetAttribute(lstm_persist, cudaFuncAttributeMaxDynamicSharedMemorySize, 131072);

    prepA<<<8448, 256>>>(Wih_f, Wih_b, h0);               // launch 1
    prepB<<<8192, 256>>>(Whh_f, Whh_b);                   // launch 2
    gemm1<<<dim3(32, 256), 256>>>(sent, embed, b_f, b_b);  // launch 3
    lstm_persist<<<128, 128, 131072>>>(c0);               // launch 4
    feats_kernel<<<2048, 256>>>(W_tag, b_tag);            // launch 5
    viterbi_kernel<<<64, 32>>>(trans, out);               // launch 6
}

// round 10
// speedup vs baseline: 2.4203x; 2.4203x over previous
#include <cuda_runtime.h>
#include <cuda_bf16.h>
#include <cstdint>

// BiLSTM-CRF forward, all fp32 (Viterbi argmax stability forbids low precision).
// Persistent recurrence: per-warp private h staging (no intra-step block syncs),
// dataflow group counters instead of a monolithic grid barrier.
//
// Shapes: V=50000 E=512 H=512 HD=1024 B=64 L=512 T=16, START=14 STOP=15

#define NEGV -10000.0f

typedef unsigned long long u64;

// smem float offsets for lstm_persist
#define SMW 0        // Ws  [0,16384)        512 x 32 gate-interleaved weights
#define SMH 16384    // Hs  [16384,49152)    16 warps x 2048 (128k x 16b tile)
#define SMR 49152    // Red [49152,57344)    4096 u64 partial sums
#define SMEM_BYTES (57344 * 4)

// ---------------- scratch (__device__ globals) ----------------------------
__device__ float g_G[(size_t)32768 * 4096];       // input-proj gates [l*64+b][dir*2048+g*512+h]
__device__ float g_Wt[(size_t)512 * 4096];        // Wih^T combined  [k][n]
__device__ float g_WhT[2][(size_t)512 * 2048];    // Whh^T per dir   [k][g*512+h]
__device__ float g_h[2][2][512][64];              // [parity][dir][k][b]
__device__ float g_hrow[(size_t)32768 * 1024];    // [l*64+b][dir*512+h]
__device__ float g_feats[(size_t)64 * 512 * 16];  // [b][l][t]
__device__ unsigned g_gcnt[2][4];                 // per (dir, k-quarter) completion counters

// ---------------- helpers ---------------------------------------------------
__device__ __forceinline__ void ffma2(u64 &d, u64 a, u64 b) {
    asm("fma.rn.f32x2 %0, %1, %2, %0;" : "+l"(d) : "l"(a), "l"(b));
}
__device__ __forceinline__ u64 pack2(float x) {
    u64 r; asm("mov.b64 %0, {%1, %1};" : "=l"(r) : "f"(x)); return r;
}
__device__ __forceinline__ float2 unpack2(u64 v) {
    float2 f; asm("mov.b64 {%0, %1}, %2;" : "=f"(f.x), "=f"(f.y) : "l"(v)); return f;
}
__device__ __forceinline__ float sigf(float x) { return 1.0f / (1.0f + expf(-x)); }
__device__ __forceinline__ void cp16(unsigned dst_sm, const float* src) {
    asm volatile("cp.async.cg.shared.global [%0], [%1], 16;\n" :: "r"(dst_sm), "l"(src));
}
template <int N> __device__ __forceinline__ void cp_wait() {
    asm volatile("cp.async.wait_group %0;\n" :: "n"(N) : "memory");
}
__device__ __forceinline__ void cp_commit() {
    asm volatile("cp.async.commit_group;\n" ::: "memory");
}
__device__ __forceinline__ unsigned ld_acq(const unsigned* p) {
    unsigned v; asm volatile("ld.acquire.gpu.global.u32 %0, [%1];" : "=r"(v) : "l"(p) : "memory");
    return v;
}

// ---------------- prep kernels ---------------------------------------------
__global__ void prepA(const float* __restrict__ wf, const float* __restrict__ wb,
                      const float* __restrict__ h0) {
    int idx = blockIdx.x * 256 + threadIdx.x;
    if (idx < 8) ((unsigned*)g_gcnt)[idx] = 0;
    if (idx < 2097152) {                       // 512*4096
        int k = idx >> 12, n = idx & 4095;
        g_Wt[idx] = (n < 2048) ? wf[n * 512 + k] : wb[(n - 2048) * 512 + k];
    } else {
        int r2 = idx - 2097152;                // 2*512*64: transpose h0 -> [k][b]
        if (r2 < 65536) {
            int dir = r2 >> 15; int r = r2 & 32767;
            int k = r >> 6, b = r & 63;
            g_h[0][dir][k][b] = h0[((size_t)dir * 64 + b) * 512 + k];
        }
    }
}
__global__ void prepB(const float* __restrict__ whf, const float* __restrict__ whb) {
    int idx = blockIdx.x * 256 + threadIdx.x;  // 2*512*2048
    int dir = idx >> 20; int r = idx & ((1 << 20) - 1);
    int k = r >> 11, n = r & 2047;
    const float* w = dir ? whb : whf;
    g_WhT[dir][(size_t)k * 2048 + n] = w[n * 512 + k];
}

// ---------------- input projection GEMM (cp.async 2-stage, unchanged) -------
__global__ void __launch_bounds__(256) gemm1(const int* __restrict__ sent,
                                             const float* __restrict__ embed,
                                             const float* __restrict__ bf,
                                             const float* __restrict__ bb) {
    __shared__ float As[2][128][16];
    __shared__ float Bs[2][16][128];
    __shared__ int toks[128];
    int tid = threadIdx.x;
    int n0 = blockIdx.x * 128;
    int m0 = blockIdx.y * 128;
    if (tid < 128) { int m = m0 + tid; toks[tid] = sent[(m & 63) * 512 + (m >> 6)]; }
    __syncthreads();
    int tx = tid & 15, ty = tid >> 4;
    unsigned smA = (unsigned)__cvta_generic_to_shared(&As[0][0][0]);
    unsigned smB = (unsigned)__cvta_generic_to_shared(&Bs[0][0][0]);

    u64 acc[8][4];
#pragma unroll
    for (int i = 0; i < 8; i++)
#pragma unroll
        for (int j = 0; j < 4; j++) acc[i][j] = 0ull;

    auto issue = [&](int k0, int buf) {
#pragma unroll
        for (int r = 0; r < 2; r++) {
            int idx = tid * 2 + r;
            int am = idx >> 2, aq = idx & 3;
            cp16(smA + (unsigned)(((buf * 128 + am) * 16 + aq * 4) * 4),
                 embed + (size_t)toks[am] * 512 + k0 + aq * 4);
            int bk = idx >> 5, bn = idx & 31;
            cp16(smB + (unsigned)(((buf * 16 + bk) * 128 + bn * 4) * 4),
                 g_Wt + (size_t)(k0 + bk) * 4096 + n0 + bn * 4);
        }
        cp_commit();
    };

    issue(0, 0);
    for (int c = 0; c < 32; c++) {
        cp_wait<0>();
        __syncthreads();
        if (c < 31) issue((c + 1) * 16, (c + 1) & 1);
        const int buf = c & 1;
#pragma unroll
        for (int k = 0; k < 16; k++) {
            u64 bv[4];
#pragma unroll
            for (int j = 0; j < 4; j++)
                bv[j] = *(const u64*)&Bs[buf][k][(j * 16 + tx) * 2];
#pragma unroll
            for (int i = 0; i < 8; i++) {
                u64 av = pack2(As[buf][ty * 8 + i][k]);
#pragma unroll
                for (int j = 0; j < 4; j++) ffma2(acc[i][j], av, bv[j]);
            }
        }
    }
#pragma unroll
    for (int j = 0; j < 4; j++) {
        int n = n0 + (j * 16 + tx) * 2;
        float2 bias;
        bias.x = (n < 2048) ? bf[n] : bb[n - 2048];
        bias.y = (n + 1 < 2048) ? bf[n + 1] : bb[n + 1 - 2048];
#pragma unroll
        for (int i = 0; i < 8; i++) {
            float2 v = unpack2(acc[i][j]);
            size_t row = (size_t)(m0 + ty * 8 + i);
            *(float2*)&g_G[row * 4096 + n] = make_float2(v.x + bias.x, v.y + bias.y);
        }
    }
}

// ---------------- persistent LSTM recurrence --------------------------------
// 128 blocks = 2 dirs x 64 h-tiles (8 h-cols). 512 threads = 16 warps.
// warp = (k-quarter kh, b-quarter bq): stages its private 128k x 16b h tile via
// cp.async, computes gate partials for its cells. One smem exchange + 2
// syncthreads per step. Cross-block sync via per-(dir,k-quarter) counters.
__global__ void __launch_bounds__(512, 1) lstm_persist(const float* __restrict__ c0) {
    extern __shared__ float smf[];
    const int tid  = threadIdx.x;
    const int lane = tid & 31;
    const int w    = tid >> 5;
    const int kh   = w >> 2;        // k-quarter 0..3
    const int bq   = w & 3;         // b-quarter 0..3
    const int bp   = lane >> 2;     // 0..7 (b-pair within 16)
    const int hp   = lane & 3;      // 0..3 (h-pair)
    const int dir  = blockIdx.x >> 6;
    const int ht   = blockIdx.x & 63;
    const int h0   = ht * 8;

    // weights, gate-interleaved: Ws[k*32 + hp*8 + g*2 + ci]
    const float* Wd = g_WhT[dir];
    for (int i = tid; i < 16384; i += 512) {
        int k = i >> 5, c = i & 31;
        smf[SMW + i] = Wd[(size_t)k * 2048 + ((c >> 1) & 3) * 512 + h0 + 2 * (c >> 3) + (c & 1)];
    }
    // owner mapping (tid<256): output (b=ob, h-pair=ohp), both ci
    const int ob = tid >> 2, ohp = tid & 3;
    float2 creg = make_float2(0.f, 0.f);
    if (tid < 256)
        creg = *(const float2*)&c0[((size_t)dir * 64 + ob) * 512 + h0 + 2 * ohp];
    __syncthreads();

    float* Hbuf = smf + SMH + w * 2048;          // [128 k][16 b]
    unsigned smHb = (unsigned)__cvta_generic_to_shared(Hbuf);
    u64* red = (u64*)(smf + SMR);
    const float* Wr = smf + SMW + (kh * 128) * 32 + hp * 8;
    const unsigned* cnt = &g_gcnt[dir][kh];

    for (int t = 0; t < 512; t++) {
        const int p = t & 1;
        const int l = dir ? (511 - t) : t;

        // owners: G prefetch into registers (consumed post-reduction)
        float2 gpre[4];
        if (tid < 256) {
            const float* Gp = g_G + ((size_t)l * 64 + ob) * 4096
                            + (size_t)dir * 2048 + h0 + 2 * ohp;
#pragma unroll
            for (int g = 0; g < 4; g++) gpre[g] = __ldcg((const float2*)(Gp + g * 512));
        }

        // dataflow wait: producers of this k-quarter must have completed t steps
        if (t) {
            const unsigned need = 16u * (unsigned)t;
            while (ld_acq(cnt) < need) {}
        }
        // stage private tile: k rows [kh*128, +128), b cols [bq*16, +16)
        const float* hsrc = &g_h[p][dir][kh * 128][bq * 16];
#pragma unroll
        for (int i = 0; i < 16; i++) {
            int idx = i * 32 + lane;
            int kk = idx >> 2, seg = idx & 3;
            cp16(smHb + (unsigned)(kk * 64 + seg * 16), hsrc + (size_t)kk * 64 + seg * 4);
        }
        cp_commit();
        cp_wait<0>();
        __syncwarp();

        u64 acc[2][4];
#pragma unroll
        for (int bi = 0; bi < 2; bi++)
#pragma unroll
            for (int g = 0; g < 4; g++) acc[bi][g] = 0ull;

#pragma unroll 8
        for (int kk = 0; kk < 128; kk++) {
            float2 h2 = *(const float2*)(Hbuf + kk * 16 + 2 * bp);
            u64 a0 = pack2(h2.x), a1 = pack2(h2.y);
            const float* wk = Wr + kk * 32;
            ulonglong2 wA = *(const ulonglong2*)(wk);
            ulonglong2 wB = *(const ulonglong2*)(wk + 4);
            ffma2(acc[0][0], a0, wA.x); ffma2(acc[1][0], a1, wA.x);
            ffma2(acc[0][1], a0, wA.y); ffma2(acc[1][1], a1, wA.y);
            ffma2(acc[0][2], a0, wB.x); ffma2(acc[1][2], a1, wB.x);
            ffma2(acc[0][3], a0, wB.y); ffma2(acc[1][3], a1, wB.y);
        }

        // publish partials
        {
            u64* rp = red + (size_t)tid * 8;
#pragma unroll
            for (int g = 0; g < 4; g++) { rp[g] = acc[0][g]; rp[4 + g] = acc[1][g]; }
        }
        __syncthreads();

        // owners: reduce 4 k-quarters + fused LSTM pointwise
        if (tid < 256) {
            const int bqp = ob >> 4, bpp = (ob & 15) >> 1, bi = ob & 1;
            const int lanep = bpp * 4 + ohp;
            float2 s[4] = {make_float2(0.f,0.f),make_float2(0.f,0.f),
                           make_float2(0.f,0.f),make_float2(0.f,0.f)};
#pragma unroll
            for (int k4 = 0; k4 < 4; k4++) {
                const u64* q = red + ((size_t)((k4 * 4 + bqp) * 32 + lanep)) * 8 + bi * 4;
#pragma unroll
                for (int g = 0; g < 4; g++) {
                    float2 v = unpack2(q[g]);
                    s[g].x += v.x; s[g].y += v.y;
                }
            }
            float hc[2];
#pragma unroll
            for (int ci = 0; ci < 2; ci++) {
                float iv = (ci ? s[0].y : s[0].x) + (ci ? gpre[0].y : gpre[0].x);
                float fv = (ci ? s[1].y : s[1].x) + (ci ? gpre[1].y : gpre[1].x);
                float gg = (ci ? s[2].y : s[2].x) + (ci ? gpre[2].y : gpre[2].x);
                float ov = (ci ? s[3].y : s[3].x) + (ci ? gpre[3].y : gpre[3].x);
                float cprev = ci ? creg.y : creg.x;
                float cn = sigf(fv) * cprev + sigf(iv) * tanhf(gg);
                if (ci) creg.y = cn; else creg.x = cn;
                hc[ci] = sigf(ov) * tanhf(cn);
            }
            *(float2*)&g_hrow[((size_t)l * 64 + ob) * 1024 + dir * 512 + h0 + 2 * ohp] =
                make_float2(hc[0], hc[1]);
            float* hn = &g_h[p ^ 1][dir][0][0];
            hn[(h0 + 2 * ohp) * 64 + ob]     = hc[0];
            hn[(h0 + 2 * ohp + 1) * 64 + ob] = hc[1];
        }
        __syncthreads();

        // publish completion of step t
        if (t != 511 && tid == 0) {
            asm volatile("membar.gl;" ::: "memory");
            asm volatile("red.release.gpu.global.add.u32 [%0], %1;"
                         :: "l"(&g_gcnt[dir][ht >> 4]), "r"(1u) : "memory");
        }
    }
}

// ---------------- tag projection ---------------------------------------------
__global__ void __launch_bounds__(256) feats_kernel(const float* __restrict__ Wtag,
                                                    const float* __restrict__ btag) {
    int idx = blockIdx.x * 256 + threadIdx.x;   // 64*512*16
    int t = idx & 15;
    int l = (idx >> 4) & 511;
    int b = idx >> 13;
    const float4* hr = (const float4*)(g_hrow + (size_t)(l * 64 + b) * 1024);
    const float4* wr = (const float4*)(Wtag + (size_t)t * 1024);
    float a0 = 0.f, a1 = 0.f;
#pragma unroll 8
    for (int k = 0; k < 256; k += 2) {
        float4 x = hr[k],     w = wr[k];
        float4 y = hr[k + 1], v = wr[k + 1];
        a0 += x.x * w.x + x.y * w.y + x.z * w.z + x.w * w.w;
        a1 += y.x * v.x + y.y * v.y + y.z * v.z + y.w * v.w;
    }
    g_feats[((size_t)b * 512 + l) * 16 + t] = a0 + a1 + btag[t];
}

// ---------------- Viterbi -----------------------------------------------------
__global__ void __launch_bounds__(32) viterbi_kernel(const float* __restrict__ trans,
                                                     float* __restrict__ out) {
    int b = blockIdx.x;
    int lane = threadIdx.x;
    __shared__ unsigned char bp[512][16];
    __shared__ float smax[16];
    bool active = lane < 16;
    int row = active ? lane : 15;
    float tr[16];
#pragma unroll
    for (int j = 0; j < 16; j++) tr[j] = trans[row * 16 + j];
    float fv = (lane == 14) ? 0.0f : NEGV;   // START=14

    const float* fb = g_feats + (size_t)b * 512 * 16;
    for (int l = 0; l < 512; l++) {
        float best = -3.4e38f;
        int arg = 0;
#pragma unroll
        for (int j = 0; j < 16; j++) {
            float s = __shfl_sync(0xffffffffu, fv, j) + tr[j];
            if (s > best) { best = s; arg = j; }
        }
        float nf = best + fb[l * 16 + row];
        if (active) bp[l][lane] = (unsigned char)arg;
        fv = nf;
    }
    float term = fv + trans[15 * 16 + row];  // STOP=15
    if (active) smax[lane] = term;
    __syncwarp();
    if (lane == 0) {
        float best = smax[0]; int tag = 0;
        for (int j = 1; j < 16; j++) if (smax[j] > best) { best = smax[j]; tag = j; }
        out[b] = best;
        for (int l = 511; l >= 0; l--) {
            out[64 + b * 512 + l] = (float)tag;
            tag = bp[l][tag];
        }
    }
}

// ---------------- launch -------------------------------------------------------
extern "C" void kernel_launch(void* const* d_in, const int* in_sizes, int n_in,
                              void* d_out, int out_size) {
    const int*   sent  = (const int*)d_in[0];
    const float* embed = (const float*)d_in[1];
    const float* Wih_f = (const float*)d_in[2];
    const float* Whh_f = (const float*)d_in[3];
    const float* b_f   = (const float*)d_in[4];
    const float* Wih_b = (const float*)d_in[5];
    const float* Whh_b = (const float*)d_in[6];
    const float* b_b   = (const float*)d_in[7];
    const float* h0    = (const float*)d_in[8];
    const float* c0    = (const float*)d_in[9];
    const float* W_tag = (const float*)d_in[10];
    const float* b_tag = (const float*)d_in[11];
    const float* trans = (const float*)d_in[12];
    float* out = (float*)d_out;

    cudaFuncSetAttribute(lstm_persist, cudaFuncAttributeMaxDynamicSharedMemorySize, SMEM_BYTES);

    prepA<<<8448, 256>>>(Wih_f, Wih_b, h0);               // launch 1
    prepB<<<8192, 256>>>(Whh_f, Whh_b);                   // launch 2
    gemm1<<<dim3(32, 256), 256>>>(sent, embed, b_f, b_b);  // launch 3
    lstm_persist<<<128, 512, SMEM_BYTES>>>(c0);           // launch 4
    feats_kernel<<<2048, 256>>>(W_tag, b_tag);            // launch 5
    viterbi_kernel<<<64, 32>>>(trans, out);               // launch 6
}

// round 12
// speedup vs baseline: 2.4951x; 1.0309x over previous
#include <cuda_runtime.h>
#include <cuda_bf16.h>
#include <cstdint>

// BiLSTM-CRF forward, all fp32 (Viterbi argmax stability forbids low precision).
// Persistent recurrence rebuilt around the L1tex-wavefront bottleneck found in
// R4-R9: thread = 8b x h-pair (8x weight reuse per fetch), weights L1-resident
// via ldca, h coalesced ldcg, smem only for the cross-warp k-reduction.
// R11: fixes R10's weight-pointer unit bug (wrow+2 -> wrow+1).
//
// Shapes: V=50000 E=512 H=512 HD=1024 B=64 L=512 T=16, START=14 STOP=15

#define NEGV -10000.0f

typedef unsigned long long u64;

// ---------------- scratch (__device__ globals) ----------------------------
__device__ float g_G[(size_t)32768 * 4096];       // input-proj gates [l*64+b][dir*2048+g*512+h]
__device__ float g_Wt[(size_t)512 * 4096];        // Wih^T combined  [k][n]
__device__ float g_Whi[2][(size_t)64 * 512 * 32]; // Whh interleaved [dir][ht][k][hp][g][ci]
__device__ float g_h[2][2][512][64];              // [parity][dir][k][b]
__device__ float g_hrow[(size_t)32768 * 1024];    // [l*64+b][dir*512+h]
__device__ float g_feats[(size_t)64 * 512 * 16];  // [b][l][t]
__device__ unsigned g_bar[2];                     // per-dir step barrier

// ---------------- helpers ---------------------------------------------------
__device__ __forceinline__ void ffma2(u64 &d, u64 a, u64 b) {
    asm("fma.rn.f32x2 %0, %1, %2, %0;" : "+l"(d) : "l"(a), "l"(b));
}
__device__ __forceinline__ u64 addf2(u64 a, u64 b) {
    u64 r; asm("add.rn.f32x2 %0, %1, %2;" : "=l"(r) : "l"(a), "l"(b)); return r;
}
__device__ __forceinline__ u64 pack2(float x) {
    u64 r; asm("mov.b64 %0, {%1, %1};" : "=l"(r) : "f"(x)); return r;
}
__device__ __forceinline__ float2 unpack2(u64 v) {
    float2 f; asm("mov.b64 {%0, %1}, %2;" : "=f"(f.x), "=f"(f.y) : "l"(v)); return f;
}
__device__ __forceinline__ float sigf(float x) { return 1.0f / (1.0f + expf(-x)); }
__device__ __forceinline__ void cp16(unsigned dst_sm, const float* src) {
    asm volatile("cp.async.cg.shared.global [%0], [%1], 16;\n" :: "r"(dst_sm), "l"(src));
}
template <int N> __device__ __forceinline__ void cp_wait() {
    asm volatile("cp.async.wait_group %0;\n" :: "n"(N) : "memory");
}
__device__ __forceinline__ void cp_commit() {
    asm volatile("cp.async.commit_group;\n" ::: "memory");
}
__device__ __forceinline__ void bar_arrive(unsigned* p) {
    asm volatile("red.release.gpu.global.add.u32 [%0], %1;" :: "l"(p), "r"(1u) : "memory");
}
__device__ __forceinline__ unsigned ld_acq(const unsigned* p) {
    unsigned v; asm volatile("ld.acquire.gpu.global.u32 %0, [%1];" : "=r"(v) : "l"(p) : "memory");
    return v;
}

// ---------------- prep kernels ---------------------------------------------
__global__ void prepA(const float* __restrict__ wf, const float* __restrict__ wb,
                      const float* __restrict__ h0) {
    int idx = blockIdx.x * 256 + threadIdx.x;
    if (idx < 2) g_bar[idx] = 0;
    if (idx < 2097152) {                       // 512*4096
        int k = idx >> 12, n = idx & 4095;
        g_Wt[idx] = (n < 2048) ? wf[n * 512 + k] : wb[(n - 2048) * 512 + k];
    } else {
        int r2 = idx - 2097152;                // 2*512*64: transpose h0 -> [k][b]
        if (r2 < 65536) {
            int dir = r2 >> 15; int r = r2 & 32767;
            int k = r >> 6, b = r & 63;
            g_h[0][dir][k][b] = h0[((size_t)dir * 64 + b) * 512 + k];
        }
    }
}
// Whh re-layout: [dir][ht][k][hp][g][ci], row of 32 floats per (ht,k)
__global__ void prepB(const float* __restrict__ whf, const float* __restrict__ whb) {
    int idx = blockIdx.x * 256 + threadIdx.x;  // 2*64*512*32 = 2097152
    int dir = idx >> 20; int r = idx & ((1 << 20) - 1);
    int ht = r >> 14;
    int r2 = r & 16383;
    int k  = r2 >> 5;
    int c  = r2 & 31;
    int hp = c >> 3, g = (c >> 1) & 3, ci = c & 1;
    int n  = g * 512 + ht * 8 + hp * 2 + ci;
    const float* w = dir ? whb : whf;
    g_Whi[dir][r] = w[(size_t)n * 512 + k];
}

// ---------------- input projection GEMM (cp.async 2-stage) ------------------
__global__ void __launch_bounds__(256) gemm1(const int* __restrict__ sent,
                                             const float* __restrict__ embed,
                                             const float* __restrict__ bf,
                                             const float* __restrict__ bb) {
    __shared__ float As[2][128][16];
    __shared__ float Bs[2][16][128];
    __shared__ int toks[128];
    int tid = threadIdx.x;
    int n0 = blockIdx.x * 128;
    int m0 = blockIdx.y * 128;
    if (tid < 128) { int m = m0 + tid; toks[tid] = sent[(m & 63) * 512 + (m >> 6)]; }
    __syncthreads();
    int tx = tid & 15, ty = tid >> 4;
    unsigned smA = (unsigned)__cvta_generic_to_shared(&As[0][0][0]);
    unsigned smB = (unsigned)__cvta_generic_to_shared(&Bs[0][0][0]);

    u64 acc[8][4];
#pragma unroll
    for (int i = 0; i < 8; i++)
#pragma unroll
        for (int j = 0; j < 4; j++) acc[i][j] = 0ull;

    auto issue = [&](int k0, int buf) {
#pragma unroll
        for (int r = 0; r < 2; r++) {
            int idx = tid * 2 + r;
            int am = idx >> 2, aq = idx & 3;
            cp16(smA + (unsigned)(((buf * 128 + am) * 16 + aq * 4) * 4),
                 embed + (size_t)toks[am] * 512 + k0 + aq * 4);
            int bk = idx >> 5, bn = idx & 31;
            cp16(smB + (unsigned)(((buf * 16 + bk) * 128 + bn * 4) * 4),
                 g_Wt + (size_t)(k0 + bk) * 4096 + n0 + bn * 4);
        }
        cp_commit();
    };

    issue(0, 0);
    for (int c = 0; c < 32; c++) {
        cp_wait<0>();
        __syncthreads();
        if (c < 31) issue((c + 1) * 16, (c + 1) & 1);
        const int buf = c & 1;
#pragma unroll
        for (int k = 0; k < 16; k++) {
            u64 bv[4];
#pragma unroll
            for (int j = 0; j < 4; j++)
                bv[j] = *(const u64*)&Bs[buf][k][(j * 16 + tx) * 2];
#pragma unroll
            for (int i = 0; i < 8; i++) {
                u64 av = pack2(As[buf][ty * 8 + i][k]);
#pragma unroll
                for (int j = 0; j < 4; j++) ffma2(acc[i][j], av, bv[j]);
            }
        }
    }
#pragma unroll
    for (int j = 0; j < 4; j++) {
        int n = n0 + (j * 16 + tx) * 2;
        float2 bias;
        bias.x = (n < 2048) ? bf[n] : bb[n - 2048];
        bias.y = (n + 1 < 2048) ? bf[n + 1] : bb[n + 1 - 2048];
#pragma unroll
        for (int i = 0; i < 8; i++) {
            float2 v = unpack2(acc[i][j]);
            size_t row = (size_t)(m0 + ty * 8 + i);
            *(float2*)&g_G[row * 4096 + n] = make_float2(v.x + bias.x, v.y + bias.y);
        }
    }
}

// ---------------- persistent LSTM recurrence --------------------------------
// 128 blocks = 2 dirs x 64 h-tiles (8 h-cols). 256 threads = 8 warps; warp =
// k-eighth (64 k); lane = (b-group of 8, h-pair). Weights from L1 (ldca),
// h coalesced ldcg with register ring, smem only for the k-reduction (64KB).
__global__ void __launch_bounds__(256, 1) lstm_persist(const float* __restrict__ c0) {
    extern __shared__ float smf[];
    u64* red = (u64*)smf;                      // 8192 u64 = 64KB
    const int tid  = threadIdx.x;
    const int lane = tid & 31;
    const int kq   = tid >> 5;        // k-eighth 0..7
    const int bg   = lane >> 2;       // 0..7 (b-group of 8)
    const int hp   = lane & 3;        // 0..3 (h-pair)
    const int dir  = blockIdx.x >> 6;
    const int ht   = blockIdx.x & 63;
    const int h0   = ht * 8;
    // every thread is also an epilogue owner: (ob, ohp)
    const int ob = tid >> 2, ohp = tid & 3;

    const float* Wp = g_Whi[dir] + ((size_t)ht * 512 + kq * 64) * 32;

    float2 creg = *(const float2*)&c0[((size_t)dir * 64 + ob) * 512 + h0 + 2 * ohp];

    for (int t = 0; t < 512; t++) {
        const int p = t & 1;
        const int l = dir ? (511 - t) : t;

        // G prefetch into registers (consumed post-reduction)
        float2 gpre[4];
        {
            const float* Gp = g_G + ((size_t)l * 64 + ob) * 4096
                            + (size_t)dir * 2048 + h0 + 2 * ohp;
#pragma unroll
            for (int g = 0; g < 4; g++) gpre[g] = __ldcg((const float2*)(Gp + g * 512));
        }

        const float* hb = &g_h[p][dir][kq * 64][bg * 8];   // row stride 64 floats

        u64 acc[8][4];
#pragma unroll
        for (int b = 0; b < 8; b++)
#pragma unroll
            for (int g = 0; g < 4; g++) acc[b][g] = 0ull;

        // h register ring, depth 4
        float4 hv[4][2];
#pragma unroll
        for (int i = 0; i < 4; i++) {
            hv[i][0] = __ldcg((const float4*)(hb + i * 64));
            hv[i][1] = __ldcg((const float4*)(hb + i * 64 + 4));
        }

#pragma unroll 4
        for (int kk = 0; kk < 64; kk++) {
            float4 ha = hv[kk & 3][0], hbv = hv[kk & 3][1];
            if (kk + 4 < 64) {
                hv[kk & 3][0] = __ldcg((const float4*)(hb + (kk + 4) * 64));
                hv[kk & 3][1] = __ldcg((const float4*)(hb + (kk + 4) * 64 + 4));
            }
            const ulonglong2* wrow = (const ulonglong2*)(Wp + kk * 32 + hp * 8);
            ulonglong2 wA = __ldca(wrow);       // gates i,f  (h-pair packed)
            ulonglong2 wB = __ldca(wrow + 1);   // gates g,o  (FIX: +1 = +16B)
            float hs[8] = {ha.x, ha.y, ha.z, ha.w, hbv.x, hbv.y, hbv.z, hbv.w};
#pragma unroll
            for (int b = 0; b < 8; b++) {
                u64 a = pack2(hs[b]);
                ffma2(acc[b][0], a, wA.x);
                ffma2(acc[b][1], a, wA.y);
                ffma2(acc[b][2], a, wB.x);
                ffma2(acc[b][3], a, wB.y);
            }
        }

        // publish partials: red[(kq*32 + bg*4 + hp)*32 + b*4 + g]
        {
            ulonglong2* rp = (ulonglong2*)(red + (size_t)tid * 32);
#pragma unroll
            for (int b = 0; b < 8; b++) {
                rp[b * 2]     = make_ulonglong2(acc[b][0], acc[b][1]);
                rp[b * 2 + 1] = make_ulonglong2(acc[b][2], acc[b][3]);
            }
        }
        __syncthreads();

        // reduce 8 k-eighths + fused LSTM pointwise (all 256 threads own 2 cells)
        {
            const int bgp = ob >> 3, bw = ob & 7;
            u64 s[4] = {0ull, 0ull, 0ull, 0ull};
#pragma unroll
            for (int k8 = 0; k8 < 8; k8++) {
                const u64* q = red + ((size_t)(k8 * 32 + bgp * 4 + ohp)) * 32 + bw * 4;
#pragma unroll
                for (int g = 0; g < 4; g++) s[g] = addf2(s[g], q[g]);
            }
            float2 si = unpack2(s[0]), sf = unpack2(s[1]);
            float2 sg = unpack2(s[2]), so = unpack2(s[3]);
            float hc[2];
#pragma unroll
            for (int ci = 0; ci < 2; ci++) {
                float iv = (ci ? si.y : si.x) + (ci ? gpre[0].y : gpre[0].x);
                float fv = (ci ? sf.y : sf.x) + (ci ? gpre[1].y : gpre[1].x);
                float gg = (ci ? sg.y : sg.x) + (ci ? gpre[2].y : gpre[2].x);
                float ov = (ci ? so.y : so.x) + (ci ? gpre[3].y : gpre[3].x);
                float cprev = ci ? creg.y : creg.x;
                float cn = sigf(fv) * cprev + sigf(iv) * tanhf(gg);
                if (ci) creg.y = cn; else creg.x = cn;
                hc[ci] = sigf(ov) * tanhf(cn);
            }
            *(float2*)&g_hrow[((size_t)l * 64 + ob) * 1024 + dir * 512 + h0 + 2 * ohp] =
                make_float2(hc[0], hc[1]);
            float* hn = &g_h[p ^ 1][dir][0][0];
            hn[(h0 + 2 * ohp) * 64 + ob]     = hc[0];
            hn[(h0 + 2 * ohp + 1) * 64 + ob] = hc[1];
        }

        // monolithic per-dir barrier: covers h visibility AND read-completion
        if (t != 511) {
            __syncthreads();
            if (tid == 0) {
                bar_arrive(&g_bar[dir]);
                unsigned target = 64u * (unsigned)(t + 1);
                while (ld_acq(&g_bar[dir]) < target) { }
            }
            __syncthreads();
        }
    }
}

// ---------------- tag projection ---------------------------------------------
__global__ void __launch_bounds__(256) feats_kernel(const float* __restrict__ Wtag,
                                                    const float* __restrict__ btag) {
    int idx = blockIdx.x * 256 + threadIdx.x;   // 64*512*16
    int t = idx & 15;
    int l = (idx >> 4) & 511;
    int b = idx >> 13;
    const float4* hr = (const float4*)(g_hrow + (size_t)(l * 64 + b) * 1024);
    const float4* wr = (const float4*)(Wtag + (size_t)t * 1024);
    float a0 = 0.f, a1 = 0.f;
#pragma unroll 8
    for (int k = 0; k < 256; k += 2) {
        float4 x = hr[k],     w = wr[k];
        float4 y = hr[k + 1], v = wr[k + 1];
        a0 += x.x * w.x + x.y * w.y + x.z * w.z + x.w * w.w;
        a1 += y.x * v.x + y.y * v.y + y.z * v.z + y.w * v.w;
    }
    g_feats[((size_t)b * 512 + l) * 16 + t] = a0 + a1 + btag[t];
}

// ---------------- Viterbi -----------------------------------------------------
__global__ void __launch_bounds__(32) viterbi_kernel(const float* __restrict__ trans,
                                                     float* __restrict__ out) {
    int b = blockIdx.x;
    int lane = threadIdx.x;
    __shared__ unsigned char bp[512][16];
    __shared__ float smax[16];
    bool active = lane < 16;
    int row = active ? lane : 15;
    float tr[16];
#pragma unroll
    for (int j = 0; j < 16; j++) tr[j] = trans[row * 16 + j];
    float fv = (lane == 14) ? 0.0f : NEGV;   // START=14

    const float* fb = g_feats + (size_t)b * 512 * 16;
    for (int l = 0; l < 512; l++) {
        float best = -3.4e38f;
        int arg = 0;
#pragma unroll
        for (int j = 0; j < 16; j++) {
            float s = __shfl_sync(0xffffffffu, fv, j) + tr[j];
            if (s > best) { best = s; arg = j; }
        }
        float nf = best + fb[l * 16 + row];
        if (active) bp[l][lane] = (unsigned char)arg;
        fv = nf;
    }
    float term = fv + trans[15 * 16 + row];  // STOP=15
    if (active) smax[lane] = term;
    __syncwarp();
    if (lane == 0) {
        float best = smax[0]; int tag = 0;
        for (int j = 1; j < 16; j++) if (smax[j] > best) { best = smax[j]; tag = j; }
        out[b] = best;
        for (int l = 511; l >= 0; l--) {
            out[64 + b * 512 + l] = (float)tag;
            tag = bp[l][tag];
        }
    }
}

// ---------------- launch -------------------------------------------------------
extern "C" void kernel_launch(void* const* d_in, const int* in_sizes, int n_in,
                              void* d_out, int out_size) {
    const int*   sent  = (const int*)d_in[0];
    const float* embed = (const float*)d_in[1];
    const float* Wih_f = (const float*)d_in[2];
    const float* Whh_f = (const float*)d_in[3];
    const float* b_f   = (const float*)d_in[4];
    const float* Wih_b = (const float*)d_in[5];
    const float* Whh_b = (const float*)d_in[6];
    const float* b_b   = (const float*)d_in[7];
    const float* h0    = (const float*)d_in[8];
    const float* c0    = (const float*)d_in[9];
    const float* W_tag = (const float*)d_in[10];
    const float* b_tag = (const float*)d_in[11];
    const float* trans = (const float*)d_in[12];
    float* out = (float*)d_out;

    cudaFuncSetAttribute(lstm_persist, cudaFuncAttributeMaxDynamicSharedMemorySize, 65536);

    prepA<<<8448, 256>>>(Wih_f, Wih_b, h0);               // launch 1
    prepB<<<8192, 256>>>(Whh_f, Whh_b);                   // launch 2
    gemm1<<<dim3(32, 256), 256>>>(sent, embed, b_f, b_b);  // launch 3
    lstm_persist<<<128, 256, 65536>>>(c0);                // launch 4
    feats_kernel<<<2048, 256>>>(W_tag, b_tag);            // launch 5
    viterbi_kernel<<<64, 32>>>(trans, out);               // launch 6
}